// round 9
// baseline (speedup 1.0000x reference)
#include <cuda_runtime.h>
#include <cstdint>
#include <cstddef>

#define NIMG 32
#define CIN  128
#define HH   64
#define WW   64
#define COUTC 256
#define NTILES (NIMG * 32 * 32)   // 32768 Winograd 2x2 output tiles

// scratch (allocation-free: __device__ globals)
__device__ __align__(16) unsigned char g_x8[(size_t)NIMG * HH * WW * CIN];  // packed x, [n][h][w][cin] 0/1
__device__ __align__(16) unsigned char g_v[(size_t)16 * NTILES * CIN];      // V = Bt d B, [pos][tile][cin], s8 in [-4,4]
__device__ __align__(16) unsigned char g_u[16 * COUTC * CIN];               // U = 4 G g Gt, [pos][cout][cin], s8 in [-9,9]

// ---------------- Phase A: x fp32 NCHW -> s8 NHWC (0/1) ----------------
__global__ __launch_bounds__(128) void conv_x_kernel(const float* __restrict__ x) {
    int p = blockIdx.x * 128 + threadIdx.x;        // (n,h,w) flat
    int w = p & 63, h = (p >> 6) & 63, n = p >> 12;
    const float* xp = x + (size_t)n * CIN * HH * WW + h * WW + w;
    unsigned char* op = g_x8 + (size_t)p * CIN;
#pragma unroll
    for (int c16 = 0; c16 < 8; c16++) {
        uint32_t u[4];
#pragma unroll
        for (int q = 0; q < 4; q++) {
            uint32_t pk = 0;
#pragma unroll
            for (int j = 0; j < 4; j++) {
                float v = xp[(size_t)(c16 * 16 + q * 4 + j) * (HH * WW)];
                pk |= (v != 0.0f ? 1u : 0u) << (8 * j);
            }
            u[q] = pk;
        }
        *(uint4*)(op + c16 * 16) = make_uint4(u[0], u[1], u[2], u[3]);
    }
}

// ---------------- Phase B1: input Winograd transform V = Bt d B ----------------
// One warp per tile; lane = cin-chunk of 4 (SIMD bytes). Perfectly coalesced.
__global__ __launch_bounds__(256) void wino_x_kernel() {
    int t = blockIdx.x * 256 + threadIdx.x;        // NTILES*32 threads
    int chunk = t & 31, tile = t >> 5;
    int n = tile >> 10, th = (tile >> 5) & 31, tw = tile & 31;
    const unsigned char* xn = g_x8 + (size_t)n * HH * WW * CIN + chunk * 4;

    uint32_t d[4][4];
#pragma unroll
    for (int i = 0; i < 4; i++) {
        int h = 2 * th - 1 + i;
#pragma unroll
        for (int j = 0; j < 4; j++) {
            int w = 2 * tw - 1 + j;
            d[i][j] = ((unsigned)h < 64u && (unsigned)w < 64u)
                ? *(const uint32_t*)(xn + (size_t)(h * 64 + w) * CIN) : 0u;
        }
    }
    uint32_t T[4][4], V[4][4];
#pragma unroll
    for (int j = 0; j < 4; j++) {
        T[0][j] = __vsub4(d[0][j], d[2][j]);
        T[1][j] = __vadd4(d[1][j], d[2][j]);
        T[2][j] = __vsub4(d[2][j], d[1][j]);
        T[3][j] = __vsub4(d[1][j], d[3][j]);
    }
#pragma unroll
    for (int i = 0; i < 4; i++) {
        V[i][0] = __vsub4(T[i][0], T[i][2]);
        V[i][1] = __vadd4(T[i][1], T[i][2]);
        V[i][2] = __vsub4(T[i][2], T[i][1]);
        V[i][3] = __vsub4(T[i][1], T[i][3]);
    }
#pragma unroll
    for (int i = 0; i < 4; i++)
#pragma unroll
        for (int j = 0; j < 4; j++)
            *(uint32_t*)(g_v + ((size_t)(i * 4 + j) * NTILES + tile) * CIN + chunk * 4) = V[i][j];
}

// ---------------- Phase B2: weight Winograd transform U = G2 g G2t (= 4 G g Gt) ----------------
__global__ __launch_bounds__(256) void wino_w_kernel(const float* __restrict__ wgt) {
    int t = blockIdx.x * 256 + threadIdx.x;        // COUTC*CIN threads
    if (t >= COUTC * CIN) return;
    int co = t >> 7, ci = t & 127;
    const float* g = wgt + ((size_t)co * CIN + ci) * 9;
    int gg[3][3];
#pragma unroll
    for (int r = 0; r < 3; r++)
#pragma unroll
        for (int c = 0; c < 3; c++) {
            float v = g[r * 3 + c];
            gg[r][c] = (v > 0.5f) ? 1 : (v < -0.5f ? -1 : 0);
        }
    int T[4][3];
#pragma unroll
    for (int c = 0; c < 3; c++) {
        T[0][c] = 2 * gg[0][c];
        T[1][c] = gg[0][c] + gg[1][c] + gg[2][c];
        T[2][c] = gg[0][c] - gg[1][c] + gg[2][c];
        T[3][c] = 2 * gg[2][c];
    }
#pragma unroll
    for (int i = 0; i < 4; i++) {
        int u[4];
        u[0] = 2 * T[i][0];
        u[1] = T[i][0] + T[i][1] + T[i][2];
        u[2] = T[i][0] - T[i][1] + T[i][2];
        u[3] = 2 * T[i][2];
#pragma unroll
        for (int j = 0; j < 4; j++)
            ((signed char*)g_u)[((size_t)(i * 4 + j) * COUTC + co) * CIN + ci] = (signed char)u[j];
    }
}

// ---------------- Phase C: 16-position GEMM + incremental inverse transform ----------------
// CTA: 128 couts (one half) x 64 tiles (2 tile-rows = 4 output rows x 64 cols).
//   warps 0-7 : mma.sync, tiles 0-31 (tile-row 0)
//   warps 8-15: dp4a,     tiles 32-63 (tile-row 1)
// Per pos: stream A (U, 16KB) + B (V, 8KB) via cp.async double-buffer; GEMM over cin;
// fold M into 4 Y accumulators with A-transform coeffs in {0,+-1}.
#define AB_STRIDE 144
#define BUF_A 0
#define BUF_B 18432
#define BUF_SZ 27648
#define SMEM_TOT (2 * BUF_SZ)   // 55296

__device__ __forceinline__ uint32_t smem_u32(const void* p) {
    uint32_t a;
    asm("{ .reg .u64 t; cvta.to.shared.u64 t, %1; cvt.u32.u64 %0, t; }" : "=r"(a) : "l"(p));
    return a;
}
__device__ __forceinline__ void cp16(uint32_t dst, const void* src) {
    asm volatile("cp.async.cg.shared.global [%0], [%1], 16;" :: "r"(dst), "l"(src));
}
#define CP_COMMIT() asm volatile("cp.async.commit_group;" ::: "memory")
#define CP_WAIT0()  asm volatile("cp.async.wait_group 0;" ::: "memory")

#define LDSM_X4(r, addr)                                                               \
    asm volatile("ldmatrix.sync.aligned.m8n8.x4.shared.b16 {%0,%1,%2,%3}, [%4];"       \
                 : "=r"((r)[0]), "=r"((r)[1]), "=r"((r)[2]), "=r"((r)[3])              \
                 : "r"(addr))

#define MMA_S8(d, a, b0, b1)                                                           \
    asm volatile("mma.sync.aligned.m16n8k32.row.col.s32.s8.s8.s32 "                    \
                 "{%0,%1,%2,%3}, {%4,%5,%6,%7}, {%8,%9}, {%0,%1,%2,%3};"               \
                 : "+r"((d)[0]), "+r"((d)[1]), "+r"((d)[2]), "+r"((d)[3])              \
                 : "r"((a)[0]), "r"((a)[1]), "r"((a)[2]), "r"((a)[3]),                 \
                   "r"(b0), "r"(b1))

// A^T rows of F(2,3): r0 = [1,1,1,0], r1 = [0,1,-1,-1]
__device__ __forceinline__ constexpr int CA(int r, int p) {
    return r == 0 ? (p == 3 ? 0 : 1) : (p == 0 ? 0 : (p == 1 ? 1 : -1));
}

__global__ __launch_bounds__(512, 1) void conv_mma_kernel(
    const float* __restrict__ bias, const float* __restrict__ sgn, float* __restrict__ out)
{
    extern __shared__ char smem[];
    uint32_t smem_base = smem_u32(smem);
    int tid = threadIdx.x, wid = tid >> 5, lane = tid & 31;
    int b = blockIdx.x;
    int ch  = b & 1;            // cout half
    int tbk = b >> 1;           // 0..511
    int n   = tbk >> 4;
    int th0 = (tbk & 15) * 2;   // first tile-row
    int tile_base = n * 1024 + th0 * 32;

    // ---- fill helper: A (1024 x 16B) + B (512 x 16B) for one pos ----
    auto fill = [&](int pos, uint32_t sb) {
        const unsigned char* asrc = g_u + ((size_t)pos * COUTC + ch * 128) * CIN;
#pragma unroll
        for (int q = 0; q < 2; q++) {
            int it = tid + q * 512;
            int c16 = it & 7, row = it >> 3;
            cp16(sb + BUF_A + row * AB_STRIDE + c16 * 16, asrc + row * CIN + c16 * 16);
        }
        const unsigned char* bsrc = g_v + ((size_t)pos * NTILES + tile_base) * CIN;
        {
            int c16 = tid & 7, row = tid >> 3;   // row 0..63
            cp16(sb + BUF_B + row * AB_STRIDE + c16 * 16, bsrc + row * CIN + c16 * 16);
        }
    };

    // prologue: pos 0
    fill(0, smem_base);
    CP_COMMIT();

    // per-warp addressing
    int warp_m = wid & 3;              // tensor: 4 warps-M (32 couts each)
    int warp_n = wid >> 2;             // tensor: 2 warps-N (16 tiles each); valid for wid<8
    uint32_t a_row   = (uint32_t)(warp_m * 32 + (lane & 7) + ((lane >> 3) & 1) * 8);
    uint32_t a_off   = a_row * AB_STRIDE + ((lane >> 4) & 1) * 16u;     // rel to buf A
    uint32_t b_rowlane = (uint32_t)((lane & 7) + ((lane >> 4) & 1) * 8);
    uint32_t b_off   = (uint32_t)(warp_n * 16 + b_rowlane) * AB_STRIDE + ((lane >> 3) & 1) * 16u;
    int widx = wid - 8;                // dp4a
    int cb  = (widx & 3) * 32;         // dp4a cout block
    int tbw = (widx >> 2) * 16;        // dp4a tile block (within tiles 32..63)
    int cg  = lane & 3;
    int pxg = lane >> 2;

    int Yr[64];
#pragma unroll
    for (int i = 0; i < 64; i++) Yr[i] = 0;

#pragma unroll
    for (int pos = 0; pos < 16; pos++) {
        CP_WAIT0();
        __syncthreads();
        if (pos < 15) { fill(pos + 1, smem_base + (uint32_t)((pos + 1) & 1) * BUF_SZ); CP_COMMIT(); }

        const int pr = pos >> 2, pc = pos & 3;
        uint32_t A0 = smem_base + (uint32_t)(pos & 1) * BUF_SZ + BUF_A;
        uint32_t B0 = smem_base + (uint32_t)(pos & 1) * BUF_SZ + BUF_B;

        if (wid < 8) {
            // ---------- tensor path: M[2][2][4] = 32cout x 16tile ----------
            int M[2][2][4];
#pragma unroll
            for (int i = 0; i < 2; i++)
#pragma unroll
                for (int j = 0; j < 2; j++)
#pragma unroll
                    for (int q = 0; q < 4; q++) M[i][j][q] = 0;
#pragma unroll
            for (int kc = 0; kc < 4; kc++) {
                uint32_t af[2][4];
                LDSM_X4(af[0], A0 + a_off + kc * 32);
                LDSM_X4(af[1], A0 + a_off + 16 * AB_STRIDE + kc * 32);
                uint32_t bf[4];
                LDSM_X4(bf, B0 + b_off + kc * 32);
                MMA_S8(M[0][0], af[0], bf[0], bf[1]);
                MMA_S8(M[0][1], af[0], bf[2], bf[3]);
                MMA_S8(M[1][0], af[1], bf[0], bf[1]);
                MMA_S8(M[1][1], af[1], bf[2], bf[3]);
            }
            // fold into Y: Yr[((i*2+jn)*4+reg)*4 + r*2+c]
#pragma unroll
            for (int i = 0; i < 2; i++)
#pragma unroll
                for (int jn = 0; jn < 2; jn++)
#pragma unroll
                    for (int reg = 0; reg < 4; reg++) {
                        int m = M[i][jn][reg];
                        int base = ((i * 2 + jn) * 4 + reg) * 4;
#pragma unroll
                        for (int r = 0; r < 2; r++)
#pragma unroll
                            for (int c = 0; c < 2; c++) {
                                const int k = CA(r, pr) * CA(c, pc);
                                if (k == 1)      Yr[base + r * 2 + c] += m;
                                else if (k == -1) Yr[base + r * 2 + c] -= m;
                            }
                    }
        } else {
            // ---------- dp4a path: M2[8][2] = 32cout x 16tile (tiles 32..63) ----------
            int M2[8][2];
#pragma unroll
            for (int i = 0; i < 8; i++) { M2[i][0] = 0; M2[i][1] = 0; }
#pragma unroll
            for (int k16 = 0; k16 < 8; k16++) {
                int4 xv0 = *(const int4*)(smem + (B0 - smem_base) + (32 + tbw + pxg) * AB_STRIDE + k16 * 16);
                int4 xv1 = *(const int4*)(smem + (B0 - smem_base) + (32 + tbw + pxg + 8) * AB_STRIDE + k16 * 16);
#pragma unroll
                for (int i = 0; i < 8; i++) {
                    int4 wv = *(const int4*)(smem + (A0 - smem_base) + (cb + cg + 4 * i) * AB_STRIDE + k16 * 16);
                    int s0 = M2[i][0], s1 = M2[i][1];
                    s0 = __dp4a(xv0.x, wv.x, s0); s0 = __dp4a(xv0.y, wv.y, s0);
                    s0 = __dp4a(xv0.z, wv.z, s0); s0 = __dp4a(xv0.w, wv.w, s0);
                    s1 = __dp4a(xv1.x, wv.x, s1); s1 = __dp4a(xv1.y, wv.y, s1);
                    s1 = __dp4a(xv1.z, wv.z, s1); s1 = __dp4a(xv1.w, wv.w, s1);
                    M2[i][0] = s0; M2[i][1] = s1;
                }
            }
#pragma unroll
            for (int i = 0; i < 8; i++)
#pragma unroll
                for (int j = 0; j < 2; j++) {
                    int m = M2[i][j];
                    int base = (i * 2 + j) * 4;
#pragma unroll
                    for (int r = 0; r < 2; r++)
#pragma unroll
                        for (int c = 0; c < 2; c++) {
                            const int k = CA(r, pr) * CA(c, pc);
                            if (k == 1)      Yr[base + r * 2 + c] += m;
                            else if (k == -1) Yr[base + r * 2 + c] -= m;
                        }
                }
        }
    }

    // ---- epilogue: y = Y/4 + bias; out = (y*sign >= 0). Use 4y vs -4bias (exact). ----
    if (wid < 8) {
        int gq = lane >> 2, tig = lane & 3;
#pragma unroll
        for (int i = 0; i < 2; i++)
#pragma unroll
            for (int jn = 0; jn < 2; jn++)
#pragma unroll
                for (int reg = 0; reg < 4; reg++) {
                    int hi = reg >> 1, lo = reg & 1;
                    int cout = ch * 128 + warp_m * 32 + i * 16 + hi * 8 + gq;
                    int tw = warp_n * 16 + jn * 8 + 2 * tig + lo;
                    float b4 = 4.0f * bias[cout];
                    float sv = sgn[cout];
                    int base = ((i * 2 + jn) * 4 + reg) * 4;
#pragma unroll
                    for (int r = 0; r < 2; r++) {
                        float f0 = (float)Yr[base + r * 2 + 0] + b4;
                        float f1 = (float)Yr[base + r * 2 + 1] + b4;
                        float2 o;
                        o.x = (f0 * sv >= 0.0f) ? 1.0f : 0.0f;
                        o.y = (f1 * sv >= 0.0f) ? 1.0f : 0.0f;
                        *(float2*)(out + (((size_t)n * COUTC + cout) * HH + 2 * th0 + r) * WW + 2 * tw) = o;
                    }
                }
    } else {
#pragma unroll
        for (int i = 0; i < 8; i++) {
            int cout = ch * 128 + cb + cg + 4 * i;
            float b4 = 4.0f * bias[cout];
            float sv = sgn[cout];
#pragma unroll
            for (int j = 0; j < 2; j++) {
                int tw = tbw + pxg + 8 * j;
                int base = (i * 2 + j) * 4;
#pragma unroll
                for (int r = 0; r < 2; r++) {
                    float f0 = (float)Yr[base + r * 2 + 0] + b4;
                    float f1 = (float)Yr[base + r * 2 + 1] + b4;
                    float2 o;
                    o.x = (f0 * sv >= 0.0f) ? 1.0f : 0.0f;
                    o.y = (f1 * sv >= 0.0f) ? 1.0f : 0.0f;
                    *(float2*)(out + (((size_t)n * COUTC + cout) * HH + 2 * th0 + 2 + r) * WW + 2 * tw) = o;
                }
            }
        }
    }
}

// ---------------- launch ----------------
extern "C" void kernel_launch(void* const* d_in, const int* in_sizes, int n_in,
                              void* d_out, int out_size) {
    const float* x    = (const float*)d_in[0];
    const float* wgt  = (const float*)d_in[1];
    const float* bias = (const float*)d_in[2];
    const float* sgn  = (const float*)d_in[3];
    float* out = (float*)d_out;

    cudaFuncSetAttribute(conv_mma_kernel, cudaFuncAttributeMaxDynamicSharedMemorySize, SMEM_TOT);

    conv_x_kernel<<<(NIMG * HH * WW) / 128, 128>>>(x);
    wino_x_kernel<<<(NTILES * 32) / 256, 256>>>();
    wino_w_kernel<<<(COUTC * CIN) / 256, 256>>>(wgt);
    conv_mma_kernel<<<NIMG * 16 * 2, 512, SMEM_TOT>>>(bias, sgn, out);
}